// round 4
// baseline (speedup 1.0000x reference)
#include <cuda_runtime.h>
#include <math.h>

#define DEPTH 24
#define DLAT 80
#define HEADS 8
#define DHD 64
#define INNER 512
#define FFD 160
#define BB 64
#define NNODE 128
#define ROWS (BB*NNODE)   // 8192
#define MHD 20

// ---------------- scratch (device globals; no runtime allocation) ----------------
__device__ float g_bias[BB*NNODE*NNODE];      // [64,128,128]
__device__ float g_x[ROWS*DLAT];              // residual stream
__device__ float g_qkv[ROWS*3*INNER];         // [8192,1536] : q | k | v
__device__ float g_o[ROWS*INNER];             // attention out [8192,512]
__device__ float g_u[ROWS*FFD];               // ffn hidden [8192,160]

// ---------------- packed f32x2 FMA ----------------
__device__ __forceinline__ float2 ffma2(float2 a, float2 b, float2 c) {
    float2 d;
    asm("fma.rn.f32x2 %0, %1, %2, %3;"
        : "=l"(*reinterpret_cast<unsigned long long*>(&d))
        : "l"(*reinterpret_cast<unsigned long long*>(&a)),
          "l"(*reinterpret_cast<unsigned long long*>(&b)),
          "l"(*reinterpret_cast<unsigned long long*>(&c)));
    return d;
}

// ---------------- bias: e + sp_bias ----------------
__global__ void bias_kernel(const int* __restrict__ sp_pos,
                            const int* __restrict__ edge_input,
                            const float* __restrict__ edge_emb,
                            const float* __restrict__ edge_dis_w,
                            const float* __restrict__ spatial_emb) {
    __shared__ float s_emb[64];
    __shared__ float s_w[MHD];
    __shared__ float s_sp[40];
    int t = threadIdx.x;
    if (t < 64) s_emb[t] = edge_emb[t];
    if (t < MHD) s_w[t] = edge_dis_w[t];
    if (t < 40) s_sp[t] = spatial_emb[t];
    __syncthreads();
    int idx = blockIdx.x * blockDim.x + t;
    if (idx >= BB*NNODE*NNODE) return;
    int spv = sp_pos[idx];
    int sp = (spv == 0) ? 1 : spv;
    sp = (sp > 1) ? (sp - 1) : sp;
    sp = (sp > MHD) ? MHD : sp;

    int buf[60];
    const int4* e4 = reinterpret_cast<const int4*>(edge_input + (size_t)idx * 60);
    #pragma unroll
    for (int m = 0; m < 15; m++) {
        int4 w = e4[m];
        buf[4*m+0] = w.x; buf[4*m+1] = w.y; buf[4*m+2] = w.z; buf[4*m+3] = w.w;
    }
    float acc = 0.f;
    #pragma unroll
    for (int hh = 0; hh < MHD; hh++) {
        float m = (s_emb[buf[3*hh]] + s_emb[buf[3*hh+1]] + s_emb[buf[3*hh+2]]) * (1.f/3.f);
        acc += m * s_w[hh];
    }
    g_bias[idx] = acc / (float)sp + s_sp[spv];
}

// ---------------- node embeddings ----------------
__global__ void embed_kernel(const int* __restrict__ x_nodes,
                             const int* __restrict__ indeg,
                             const int* __restrict__ outdeg,
                             const float* __restrict__ ae,
                             const float* __restrict__ ie,
                             const float* __restrict__ oe) {
    int row = blockIdx.x;
    int d = threadIdx.x;
    if (d < DLAT) {
        g_x[row*DLAT + d] = ae[x_nodes[row]*DLAT + d]
                          + ie[indeg[row]*DLAT + d]
                          + oe[outdeg[row]*DLAT + d];
    }
}

// ---------------- in-tile layernorm helper (64 rows of g_x -> Hs, normalized) ----
__device__ __forceinline__ void tile_ln(float* Hs, float* sg, float* sb,
                                        const float* __restrict__ gam,
                                        const float* __restrict__ bet,
                                        int t, int nthreads, int m0) {
    if (t < 80) { sg[t] = gam[t]; sb[t] = bet[t]; }
    for (int i = t; i < 64*20; i += nthreads) {
        int r = i / 20, c = i % 20;
        *(float4*)&Hs[r*80 + c*4] = *(const float4*)&g_x[(size_t)(m0+r)*80 + c*4];
    }
    __syncthreads();
    if (t < 64) {
        float* row = Hs + t*80;
        float s = 0.f;
        #pragma unroll 8
        for (int i = 0; i < 80; i++) s += row[i];
        float mean = s * (1.f/80.f);
        float q = 0.f;
        #pragma unroll 8
        for (int i = 0; i < 80; i++) { float d = row[i] - mean; q += d*d; }
        float inv = rsqrtf(q * (1.f/80.f) + 1e-5f);
        #pragma unroll 8
        for (int i = 0; i < 80; i++) row[i] = (row[i] - mean)*inv*sg[i] + sb[i];
    }
    __syncthreads();
}

// ---------------- qkv gemm (fused LN1): LN(g_x)[8192,80] @ [Wq|Wkv] -> g_qkv -----
// tile 64 rows x 128 cols, 128 threads, dynamic smem
#define QKV_SMEM ((64*80 + 80*128 + 160) * 4)
__global__ void __launch_bounds__(128) gemm_qkv_kernel(const float* __restrict__ Wq,
                                                       const float* __restrict__ Wkv,
                                                       const float* __restrict__ gam,
                                                       const float* __restrict__ bet) {
    extern __shared__ float smq[];
    float* Hs = smq;                 // 64*80
    float* Ws = Hs + 64*80;          // 80*128
    float* sg = Ws + 80*128;         // 80
    float* sb = sg + 80;             // 80
    int m0 = blockIdx.x * 64;
    int n0 = blockIdx.y * 128;
    int t = threadIdx.x;

    // weight tile stage (cols n0..n0+127, fully inside Wq or Wkv since 128-aligned)
    for (int i = t; i < 80*32; i += 128) {
        int k = i >> 5, c4 = i & 31;
        int n = n0 + c4*4;
        const float* src = (n < INNER) ? (Wq + (size_t)k*INNER + n)
                                       : (Wkv + (size_t)k*(2*INNER) + (n - INNER));
        *(float4*)&Ws[k*128 + c4*4] = *(const float4*)src;
    }
    tile_ln(Hs, sg, sb, gam, bet, t, 128, m0);

    int tx = t & 15, ty = t >> 4;    // 16 x 8
    float2 acc[8][4];
    #pragma unroll
    for (int r = 0; r < 8; r++)
        #pragma unroll
        for (int c = 0; c < 4; c++) acc[r][c] = make_float2(0.f, 0.f);

    #pragma unroll 4
    for (int k = 0; k < 80; k++) {
        float4 wa = *(const float4*)&Ws[k*128 + (tx << 2)];
        float4 wb = *(const float4*)&Ws[k*128 + (tx << 2) + 64];
        float2 w0 = make_float2(wa.x, wa.y), w1 = make_float2(wa.z, wa.w);
        float2 w2 = make_float2(wb.x, wb.y), w3 = make_float2(wb.z, wb.w);
        #pragma unroll
        for (int r = 0; r < 8; r++) {
            float a = Hs[(ty + (r << 3))*80 + k];
            float2 aa = make_float2(a, a);
            acc[r][0] = ffma2(aa, w0, acc[r][0]);
            acc[r][1] = ffma2(aa, w1, acc[r][1]);
            acc[r][2] = ffma2(aa, w2, acc[r][2]);
            acc[r][3] = ffma2(aa, w3, acc[r][3]);
        }
    }
    #pragma unroll
    for (int r = 0; r < 8; r++) {
        size_t row = m0 + ty + (r << 3);
        *(float4*)&g_qkv[row*1536 + n0 + (tx << 2)] =
            make_float4(acc[r][0].x, acc[r][0].y, acc[r][1].x, acc[r][1].y);
        *(float4*)&g_qkv[row*1536 + n0 + (tx << 2) + 64] =
            make_float4(acc[r][2].x, acc[r][2].y, acc[r][3].x, acc[r][3].y);
    }
}

// ---------------- ffn1 (fused LN2): gelu(LN(g_x) @ W1 + b1) -> g_u ----------------
__global__ void __launch_bounds__(128) gemm_ffn1_kernel(const float* __restrict__ W1,
                                                        const float* __restrict__ b1,
                                                        const float* __restrict__ gam,
                                                        const float* __restrict__ bet) {
    __shared__ float Hs[64*80];
    __shared__ float Ws[80*64];
    __shared__ float sg[80], sb[80];
    int m0 = blockIdx.x * 64;
    int n0 = blockIdx.y * 64;
    int t = threadIdx.x;

    for (int i = t; i < 80*64; i += 128) {
        int k = i >> 6;
        int n = n0 + (i & 63);
        Ws[i] = (n < FFD) ? W1[(size_t)k*FFD + n] : 0.f;
    }
    tile_ln(Hs, sg, sb, gam, bet, t, 128, m0);

    int tx = t & 15, ty = t >> 4;
    float2 acc[8][2];
    #pragma unroll
    for (int r = 0; r < 8; r++) { acc[r][0] = make_float2(0.f,0.f); acc[r][1] = make_float2(0.f,0.f); }

    #pragma unroll 4
    for (int k = 0; k < 80; k++) {
        float4 w = *(const float4*)&Ws[(k << 6) + (tx << 2)];
        float2 w0 = make_float2(w.x, w.y), w1 = make_float2(w.z, w.w);
        #pragma unroll
        for (int r = 0; r < 8; r++) {
            float a = Hs[(ty + (r << 3))*80 + k];
            float2 aa = make_float2(a, a);
            acc[r][0] = ffma2(aa, w0, acc[r][0]);
            acc[r][1] = ffma2(aa, w1, acc[r][1]);
        }
    }
    int ncol = n0 + (tx << 2);
    if (ncol < FFD) {
        float4 bv = *(const float4*)&b1[ncol];
        #pragma unroll
        for (int r = 0; r < 8; r++) {
            float4 v; float vv;
            vv = acc[r][0].x + bv.x; v.x = vv*0.5f*(1.f + erff(vv*0.70710678118654752f));
            vv = acc[r][0].y + bv.y; v.y = vv*0.5f*(1.f + erff(vv*0.70710678118654752f));
            vv = acc[r][1].x + bv.z; v.z = vv*0.5f*(1.f + erff(vv*0.70710678118654752f));
            vv = acc[r][1].y + bv.w; v.w = vv*0.5f*(1.f + erff(vv*0.70710678118654752f));
            *(float4*)&g_u[(size_t)(m0 + ty + (r << 3))*FFD + ncol] = v;
        }
    }
}

// ---------------- A @ W[K,80] + bias + residual -> g_x (in place) ----------------
// mode 0: A = g_o (K=512, Wo);  mode 1: A = g_u (K=160, W2)
__global__ void __launch_bounds__(160) gemm_resid_kernel(const float* __restrict__ W,
                                                         const float* __restrict__ bias,
                                                         int mode) {
    __shared__ float As[64*33];
    __shared__ float Ws[32*80];
    const float* A = mode ? g_u : g_o;
    int K = mode ? FFD : INNER;
    int m0 = blockIdx.x * 64;
    int t = threadIdx.x;
    int tx = t % 20, ty = t / 20;
    float2 acc[8][2];
    #pragma unroll
    for (int r = 0; r < 8; r++) { acc[r][0] = make_float2(0.f,0.f); acc[r][1] = make_float2(0.f,0.f); }

    for (int k0 = 0; k0 < K; k0 += 32) {
        __syncthreads();
        for (int i = t; i < 64*32; i += 160) {
            int r = i >> 5, c = i & 31;
            As[r*33 + c] = A[(size_t)(m0 + r)*K + k0 + c];
        }
        for (int i = t; i < 32*80; i += 160) {
            Ws[i] = W[(size_t)(k0 + i/80)*80 + (i % 80)];
        }
        __syncthreads();
        #pragma unroll 4
        for (int kk = 0; kk < 32; kk++) {
            float4 w = *(const float4*)&Ws[kk*80 + (tx << 2)];
            float2 w0 = make_float2(w.x, w.y), w1 = make_float2(w.z, w.w);
            #pragma unroll
            for (int r = 0; r < 8; r++) {
                float a = As[(ty + (r << 3))*33 + kk];
                float2 aa = make_float2(a, a);
                acc[r][0] = ffma2(aa, w0, acc[r][0]);
                acc[r][1] = ffma2(aa, w1, acc[r][1]);
            }
        }
    }
    int col = tx << 2;
    float4 bsv = *(const float4*)&bias[col];
    #pragma unroll
    for (int r = 0; r < 8; r++) {
        int row = m0 + ty + (r << 3);
        float4 res = *(const float4*)&g_x[(size_t)row*80 + col];
        float4 v = make_float4(acc[r][0].x + bsv.x + res.x,
                               acc[r][0].y + bsv.y + res.y,
                               acc[r][1].x + bsv.z + res.z,
                               acc[r][1].y + bsv.w + res.w);
        *(float4*)&g_x[(size_t)row*80 + col] = v;
    }
}

// ---------------- attention: one block per (b, head) ----------------
// smem: Qt[64][132] (transposed Q, later aliased by V[128][66]),
//       Ks[128][66], Ss[128][132]
#define ATTN_SMEM ((64*132 + 128*66 + 128*132) * 4)
__global__ void __launch_bounds__(256) attn_kernel() {
    extern __shared__ float sm[];
    float* Qt = sm;                  // 64*132 = 8448 floats (aliased by Vs)
    float* Vs = sm;                  // 128*66 = 8448 floats
    float* Ks = sm + 64*132;         // 128*66
    float* Ss = Ks + 128*66;         // 128*132
    int bh = blockIdx.x;
    int b = bh >> 3, hh = bh & 7;
    int t = threadIdx.x;
    int tx = t & 15, ty = t >> 4;    // 16 x 16

    const float* qbase = g_qkv + (size_t)(b*NNODE)*1536 + hh*DHD;
    // stage Q transposed (Qt[k][i] = Q[i][k]) and K row-major (stride 66)
    for (int i = t; i < 128*32; i += 256) {
        int r = i >> 5, c2 = i & 31;
        float2 q = *(const float2*)(qbase + (size_t)r*1536 + c2*2);
        Qt[(c2*2)*132 + r]     = q.x;
        Qt[(c2*2+1)*132 + r]   = q.y;
        *(float2*)&Ks[r*66 + c2*2] = *(const float2*)(qbase + 512 + (size_t)r*1536 + c2*2);
    }
    const float* bb = g_bias + (size_t)b*NNODE*NNODE;
    for (int i = t; i < 128*128; i += 256) {
        Ss[(i >> 7)*132 + (i & 127)] = bb[i];
    }
    __syncthreads();

    // phase 1: S += scale * Q K^T ; rows ty*8..ty*8+7 (k-pair packed), cols tx+16c
    {
        float2 acc[4][8];
        #pragma unroll
        for (int p = 0; p < 4; p++)
            #pragma unroll
            for (int c = 0; c < 8; c++) acc[p][c] = make_float2(0.f, 0.f);
        #pragma unroll 2
        for (int k = 0; k < 64; k++) {
            float2 a2[4];
            #pragma unroll
            for (int p = 0; p < 4; p++)
                a2[p] = *(float2*)&Qt[k*132 + ty*8 + 2*p];
            float kb[8];
            #pragma unroll
            for (int c = 0; c < 8; c++) kb[c] = Ks[(tx + 16*c)*66 + k];
            #pragma unroll
            for (int p = 0; p < 4; p++)
                #pragma unroll
                for (int c = 0; c < 8; c++) {
                    float2 kk2 = make_float2(kb[c], kb[c]);
                    acc[p][c] = ffma2(a2[p], kk2, acc[p][c]);
                }
        }
        #pragma unroll
        for (int p = 0; p < 4; p++)
            #pragma unroll
            for (int c = 0; c < 8; c++) {
                int row = ty*8 + 2*p, col = tx + 16*c;
                Ss[row*132 + col]       += acc[p][c].x * 0.125f;
                Ss[(row+1)*132 + col]   += acc[p][c].y * 0.125f;
            }
    }
    __syncthreads();

    // stage V into Qt's space (Q dead), then softmax with all 8 warps
    for (int i = t; i < 128*32; i += 256) {
        int r = i >> 5, c2 = i & 31;
        *(float2*)&Vs[r*66 + c2*2] = *(const float2*)(qbase + 1024 + (size_t)r*1536 + c2*2);
    }
    {
        int w = t >> 5, lane = t & 31;
        for (int rr = 0; rr < 16; rr++) {
            int row = w*16 + rr;
            float4 v = *(float4*)&Ss[row*132 + lane*4];
            float mx = fmaxf(fmaxf(v.x, v.y), fmaxf(v.z, v.w));
            #pragma unroll
            for (int o = 16; o; o >>= 1) mx = fmaxf(mx, __shfl_xor_sync(0xffffffffu, mx, o));
            v.x = __expf(v.x - mx); v.y = __expf(v.y - mx);
            v.z = __expf(v.z - mx); v.w = __expf(v.w - mx);
            float s = v.x + v.y + v.z + v.w;
            #pragma unroll
            for (int o = 16; o; o >>= 1) s += __shfl_xor_sync(0xffffffffu, s, o);
            float inv = 1.f / s;
            v.x *= inv; v.y *= inv; v.z *= inv; v.w *= inv;
            *(float4*)&Ss[row*132 + lane*4] = v;
        }
    }
    __syncthreads();

    // phase 2: O = A V ; rows ty*8..+7, cols {2tx,2tx+1} and {2tx+32,2tx+33}
    {
        float2 oacc[8][2];
        #pragma unroll
        for (int rr = 0; rr < 8; rr++) { oacc[rr][0] = make_float2(0.f,0.f); oacc[rr][1] = make_float2(0.f,0.f); }
        #pragma unroll 2
        for (int j = 0; j < 128; j++) {
            float2 v0 = *(float2*)&Vs[j*66 + 2*tx];
            float2 v1 = *(float2*)&Vs[j*66 + 32 + 2*tx];
            #pragma unroll
            for (int rr = 0; rr < 8; rr++) {
                float a = Ss[(ty*8 + rr)*132 + j];
                float2 aa = make_float2(a, a);
                oacc[rr][0] = ffma2(aa, v0, oacc[rr][0]);
                oacc[rr][1] = ffma2(aa, v1, oacc[rr][1]);
            }
        }
        float* obase = g_o + (size_t)(b*NNODE)*INNER + hh*DHD;
        #pragma unroll
        for (int rr = 0; rr < 8; rr++) {
            int row = ty*8 + rr;
            *(float2*)&obase[(size_t)row*INNER + 2*tx]      = oacc[rr][0];
            *(float2*)&obase[(size_t)row*INNER + 32 + 2*tx] = oacc[rr][1];
        }
    }
}

// ---------------- final: pool, LN, linear ----------------
__global__ void final_kernel(const float* __restrict__ gam, const float* __restrict__ bet,
                             const float* __restrict__ Wf, const float* __restrict__ bf,
                             float* __restrict__ out) {
    __shared__ float p[DLAT];
    int b = blockIdx.x, d = threadIdx.x;
    if (d < DLAT) {
        float s = 0.f;
        for (int n = 0; n < NNODE; n++) s += g_x[(size_t)((b << 7) + n)*DLAT + d];
        p[d] = s * (1.f/128.f);
    }
    __syncthreads();
    if (d == 0) {
        float m = 0.f;
        for (int i = 0; i < DLAT; i++) m += p[i];
        m *= (1.f/80.f);
        float v = 0.f;
        for (int i = 0; i < DLAT; i++) { float dd = p[i] - m; v += dd*dd; }
        v *= (1.f/80.f);
        float inv = rsqrtf(v + 1e-5f);
        float acc = bf[0];
        for (int i = 0; i < DLAT; i++)
            acc += ((p[i] - m)*inv*gam[i] + bet[i]) * Wf[i];
        out[b] = acc;
    }
}

// ---------------- launcher ----------------
extern "C" void kernel_launch(void* const* d_in, const int* in_sizes, int n_in,
                              void* d_out, int out_size) {
    const int*   spatial_pos = (const int*)d_in[0];
    const int*   edge_input  = (const int*)d_in[1];
    const int*   x_nodes     = (const int*)d_in[2];
    const int*   indeg       = (const int*)d_in[3];
    const int*   outdeg      = (const int*)d_in[4];
    const float* atom_emb    = (const float*)d_in[5];
    const float* indeg_emb   = (const float*)d_in[6];
    const float* outdeg_emb  = (const float*)d_in[7];
    const float* edge_emb    = (const float*)d_in[8];
    const float* edge_dis_w  = (const float*)d_in[9];
    const float* spatial_emb = (const float*)d_in[10];
    const float* ln1_g = (const float*)d_in[11];
    const float* ln1_b = (const float*)d_in[12];
    const float* Wq    = (const float*)d_in[13];
    const float* Wkv   = (const float*)d_in[14];
    const float* Wo    = (const float*)d_in[15];
    const float* bo    = (const float*)d_in[16];
    const float* ln2_g = (const float*)d_in[17];
    const float* ln2_b = (const float*)d_in[18];
    const float* W1    = (const float*)d_in[19];
    const float* b1    = (const float*)d_in[20];
    const float* W2    = (const float*)d_in[21];
    const float* b2    = (const float*)d_in[22];
    const float* lnf_g = (const float*)d_in[23];
    const float* lnf_b = (const float*)d_in[24];
    const float* Wf    = (const float*)d_in[25];
    const float* bf    = (const float*)d_in[26];
    float* out = (float*)d_out;

    cudaFuncSetAttribute(attn_kernel, cudaFuncAttributeMaxDynamicSharedMemorySize, ATTN_SMEM);
    cudaFuncSetAttribute(gemm_qkv_kernel, cudaFuncAttributeMaxDynamicSharedMemorySize, QKV_SMEM);

    bias_kernel<<<(BB*NNODE*NNODE)/256, 256>>>(spatial_pos, edge_input, edge_emb,
                                               edge_dis_w, spatial_emb);
    embed_kernel<<<ROWS, 80>>>(x_nodes, indeg, outdeg, atom_emb, indeg_emb, outdeg_emb);

    for (int l = 0; l < DEPTH; l++) {
        gemm_qkv_kernel<<<dim3(ROWS/64, 12), 128, QKV_SMEM>>>(
            Wq + (size_t)l*DLAT*INNER, Wkv + (size_t)l*DLAT*2*INNER,
            ln1_g + l*DLAT, ln1_b + l*DLAT);
        attn_kernel<<<BB*HEADS, 256, ATTN_SMEM>>>();
        gemm_resid_kernel<<<ROWS/64, 160>>>(Wo + (size_t)l*INNER*DLAT, bo + l*DLAT, 0);
        gemm_ffn1_kernel<<<dim3(ROWS/64, 3), 128>>>(W1 + (size_t)l*DLAT*FFD, b1 + l*FFD,
                                                    ln2_g + l*DLAT, ln2_b + l*DLAT);
        gemm_resid_kernel<<<ROWS/64, 160>>>(W2 + (size_t)l*FFD*DLAT, b2 + l*DLAT, 1);
    }
    final_kernel<<<BB, 80>>>(lnf_g, lnf_b, Wf, bf, out);
}

// round 6
// speedup vs baseline: 1.1448x; 1.1448x over previous
#include <cuda_runtime.h>
#include <math.h>

#define DEPTH 24
#define DLAT 80
#define HEADS 8
#define DHD 64
#define INNER 512
#define FFD 160
#define BB 64
#define NNODE 128
#define ROWS (BB*NNODE)   // 8192
#define MHD 20

// ---------------- scratch (device globals; no runtime allocation) ----------------
__device__ float g_bias[BB*NNODE*NNODE];      // [64,128,128]
__device__ float g_x[ROWS*DLAT];              // residual stream
__device__ float g_qkv[ROWS*3*INNER];         // [8192,1536] : q | k | v
__device__ float g_o[ROWS*INNER];             // attention out [8192,512]
__device__ float g_u[ROWS*FFD];               // ffn hidden [8192,160]

// ---------------- packed f32x2 FMA ----------------
__device__ __forceinline__ float2 ffma2(float2 a, float2 b, float2 c) {
    float2 d;
    asm("fma.rn.f32x2 %0, %1, %2, %3;"
        : "=l"(*reinterpret_cast<unsigned long long*>(&d))
        : "l"(*reinterpret_cast<unsigned long long*>(&a)),
          "l"(*reinterpret_cast<unsigned long long*>(&b)),
          "l"(*reinterpret_cast<unsigned long long*>(&c)));
    return d;
}

// ---------------- bias: e + sp_bias ----------------
__global__ void bias_kernel(const int* __restrict__ sp_pos,
                            const int* __restrict__ edge_input,
                            const float* __restrict__ edge_emb,
                            const float* __restrict__ edge_dis_w,
                            const float* __restrict__ spatial_emb) {
    __shared__ float s_emb[64];
    __shared__ float s_w[MHD];
    __shared__ float s_sp[40];
    int t = threadIdx.x;
    if (t < 64) s_emb[t] = edge_emb[t];
    if (t < MHD) s_w[t] = edge_dis_w[t];
    if (t < 40) s_sp[t] = spatial_emb[t];
    __syncthreads();
    int idx = blockIdx.x * blockDim.x + t;
    if (idx >= BB*NNODE*NNODE) return;
    int spv = sp_pos[idx];
    int sp = (spv == 0) ? 1 : spv;
    sp = (sp > 1) ? (sp - 1) : sp;
    sp = (sp > MHD) ? MHD : sp;

    int buf[60];
    const int4* e4 = reinterpret_cast<const int4*>(edge_input + (size_t)idx * 60);
    #pragma unroll
    for (int m = 0; m < 15; m++) {
        int4 w = e4[m];
        buf[4*m+0] = w.x; buf[4*m+1] = w.y; buf[4*m+2] = w.z; buf[4*m+3] = w.w;
    }
    float acc = 0.f;
    #pragma unroll
    for (int hh = 0; hh < MHD; hh++) {
        float m = (s_emb[buf[3*hh]] + s_emb[buf[3*hh+1]] + s_emb[buf[3*hh+2]]) * (1.f/3.f);
        acc += m * s_w[hh];
    }
    g_bias[idx] = acc / (float)sp + s_sp[spv];
}

// ---------------- node embeddings ----------------
__global__ void embed_kernel(const int* __restrict__ x_nodes,
                             const int* __restrict__ indeg,
                             const int* __restrict__ outdeg,
                             const float* __restrict__ ae,
                             const float* __restrict__ ie,
                             const float* __restrict__ oe) {
    int row = blockIdx.x;
    int d = threadIdx.x;
    if (d < DLAT) {
        g_x[row*DLAT + d] = ae[x_nodes[row]*DLAT + d]
                          + ie[indeg[row]*DLAT + d]
                          + oe[outdeg[row]*DLAT + d];
    }
}

// ---------------- in-tile layernorm helper (64 rows of g_x -> Hs, normalized) ----
__device__ __forceinline__ void tile_ln(float* Hs, float* sg, float* sb,
                                        const float* __restrict__ gam,
                                        const float* __restrict__ bet,
                                        int t, int nthreads, int m0) {
    if (t < 80) { sg[t] = gam[t]; sb[t] = bet[t]; }
    for (int i = t; i < 64*20; i += nthreads) {
        int r = i / 20, c = i % 20;
        *(float4*)&Hs[r*80 + c*4] = *(const float4*)&g_x[(size_t)(m0+r)*80 + c*4];
    }
    __syncthreads();
    if (t < 64) {
        float* row = Hs + t*80;
        float s = 0.f;
        #pragma unroll 8
        for (int i = 0; i < 80; i++) s += row[i];
        float mean = s * (1.f/80.f);
        float q = 0.f;
        #pragma unroll 8
        for (int i = 0; i < 80; i++) { float d = row[i] - mean; q += d*d; }
        float inv = rsqrtf(q * (1.f/80.f) + 1e-5f);
        #pragma unroll 8
        for (int i = 0; i < 80; i++) row[i] = (row[i] - mean)*inv*sg[i] + sb[i];
    }
    __syncthreads();
}

// ---------------- qkv gemm (fused LN1): LN(g_x)[8192,80] @ [Wq|Wkv] -> g_qkv -----
#define QKV_SMEM ((64*80 + 80*128 + 160) * 4)
__global__ void __launch_bounds__(128) gemm_qkv_kernel(const float* __restrict__ Wq,
                                                       const float* __restrict__ Wkv,
                                                       const float* __restrict__ gam,
                                                       const float* __restrict__ bet) {
    extern __shared__ float smq[];
    float* Hs = smq;                 // 64*80
    float* Ws = Hs + 64*80;          // 80*128
    float* sg = Ws + 80*128;         // 80
    float* sb = sg + 80;             // 80
    int m0 = blockIdx.x * 64;
    int n0 = blockIdx.y * 128;
    int t = threadIdx.x;

    for (int i = t; i < 80*32; i += 128) {
        int k = i >> 5, c4 = i & 31;
        int n = n0 + c4*4;
        const float* src = (n < INNER) ? (Wq + (size_t)k*INNER + n)
                                       : (Wkv + (size_t)k*(2*INNER) + (n - INNER));
        *(float4*)&Ws[k*128 + c4*4] = *(const float4*)src;
    }
    tile_ln(Hs, sg, sb, gam, bet, t, 128, m0);

    int tx = t & 15, ty = t >> 4;    // 16 x 8
    float2 acc[8][4];
    #pragma unroll
    for (int r = 0; r < 8; r++)
        #pragma unroll
        for (int c = 0; c < 4; c++) acc[r][c] = make_float2(0.f, 0.f);

    #pragma unroll 4
    for (int k = 0; k < 80; k++) {
        float4 wa = *(const float4*)&Ws[k*128 + (tx << 2)];
        float4 wb = *(const float4*)&Ws[k*128 + (tx << 2) + 64];
        float2 w0 = make_float2(wa.x, wa.y), w1 = make_float2(wa.z, wa.w);
        float2 w2 = make_float2(wb.x, wb.y), w3 = make_float2(wb.z, wb.w);
        #pragma unroll
        for (int r = 0; r < 8; r++) {
            float a = Hs[(ty + (r << 3))*80 + k];
            float2 aa = make_float2(a, a);
            acc[r][0] = ffma2(aa, w0, acc[r][0]);
            acc[r][1] = ffma2(aa, w1, acc[r][1]);
            acc[r][2] = ffma2(aa, w2, acc[r][2]);
            acc[r][3] = ffma2(aa, w3, acc[r][3]);
        }
    }
    #pragma unroll
    for (int r = 0; r < 8; r++) {
        size_t row = m0 + ty + (r << 3);
        *(float4*)&g_qkv[row*1536 + n0 + (tx << 2)] =
            make_float4(acc[r][0].x, acc[r][0].y, acc[r][1].x, acc[r][1].y);
        *(float4*)&g_qkv[row*1536 + n0 + (tx << 2) + 64] =
            make_float4(acc[r][2].x, acc[r][2].y, acc[r][3].x, acc[r][3].y);
    }
}

// ---------------- ffn1 (fused LN2): gelu(LN(g_x) @ W1 + b1) -> g_u ----------------
__global__ void __launch_bounds__(128) gemm_ffn1_kernel(const float* __restrict__ W1,
                                                        const float* __restrict__ b1,
                                                        const float* __restrict__ gam,
                                                        const float* __restrict__ bet) {
    __shared__ float Hs[64*80];
    __shared__ float Ws[80*64];
    __shared__ float sg[80], sb[80];
    int m0 = blockIdx.x * 64;
    int n0 = blockIdx.y * 64;
    int t = threadIdx.x;

    for (int i = t; i < 80*64; i += 128) {
        int k = i >> 6;
        int n = n0 + (i & 63);
        Ws[i] = (n < FFD) ? W1[(size_t)k*FFD + n] : 0.f;
    }
    tile_ln(Hs, sg, sb, gam, bet, t, 128, m0);

    int tx = t & 15, ty = t >> 4;
    float2 acc[8][2];
    #pragma unroll
    for (int r = 0; r < 8; r++) { acc[r][0] = make_float2(0.f,0.f); acc[r][1] = make_float2(0.f,0.f); }

    #pragma unroll 4
    for (int k = 0; k < 80; k++) {
        float4 w = *(const float4*)&Ws[(k << 6) + (tx << 2)];
        float2 w0 = make_float2(w.x, w.y), w1 = make_float2(w.z, w.w);
        #pragma unroll
        for (int r = 0; r < 8; r++) {
            float a = Hs[(ty + (r << 3))*80 + k];
            float2 aa = make_float2(a, a);
            acc[r][0] = ffma2(aa, w0, acc[r][0]);
            acc[r][1] = ffma2(aa, w1, acc[r][1]);
        }
    }
    int ncol = n0 + (tx << 2);
    if (ncol < FFD) {
        float4 bv = *(const float4*)&b1[ncol];
        #pragma unroll
        for (int r = 0; r < 8; r++) {
            float4 v; float vv;
            vv = acc[r][0].x + bv.x; v.x = vv*0.5f*(1.f + erff(vv*0.70710678118654752f));
            vv = acc[r][0].y + bv.y; v.y = vv*0.5f*(1.f + erff(vv*0.70710678118654752f));
            vv = acc[r][1].x + bv.z; v.z = vv*0.5f*(1.f + erff(vv*0.70710678118654752f));
            vv = acc[r][1].y + bv.w; v.w = vv*0.5f*(1.f + erff(vv*0.70710678118654752f));
            *(float4*)&g_u[(size_t)(m0 + ty + (r << 3))*FFD + ncol] = v;
        }
    }
}

// ---------------- A @ W[K,80] + bias + residual -> g_x (in place) ----------------
__global__ void __launch_bounds__(160) gemm_resid_kernel(const float* __restrict__ W,
                                                         const float* __restrict__ bias,
                                                         int mode) {
    __shared__ float As[64*33];
    __shared__ float Ws[32*80];
    const float* A = mode ? g_u : g_o;
    int K = mode ? FFD : INNER;
    int m0 = blockIdx.x * 64;
    int t = threadIdx.x;
    int tx = t % 20, ty = t / 20;
    float2 acc[8][2];
    #pragma unroll
    for (int r = 0; r < 8; r++) { acc[r][0] = make_float2(0.f,0.f); acc[r][1] = make_float2(0.f,0.f); }

    for (int k0 = 0; k0 < K; k0 += 32) {
        __syncthreads();
        for (int i = t; i < 64*32; i += 160) {
            int r = i >> 5, c = i & 31;
            As[r*33 + c] = A[(size_t)(m0 + r)*K + k0 + c];
        }
        for (int i = t; i < 32*80; i += 160) {
            Ws[i] = W[(size_t)(k0 + i/80)*80 + (i % 80)];
        }
        __syncthreads();
        #pragma unroll 4
        for (int kk = 0; kk < 32; kk++) {
            float4 w = *(const float4*)&Ws[kk*80 + (tx << 2)];
            float2 w0 = make_float2(w.x, w.y), w1 = make_float2(w.z, w.w);
            #pragma unroll
            for (int r = 0; r < 8; r++) {
                float a = As[(ty + (r << 3))*33 + kk];
                float2 aa = make_float2(a, a);
                acc[r][0] = ffma2(aa, w0, acc[r][0]);
                acc[r][1] = ffma2(aa, w1, acc[r][1]);
            }
        }
    }
    int col = tx << 2;
    float4 bsv = *(const float4*)&bias[col];
    #pragma unroll
    for (int r = 0; r < 8; r++) {
        int row = m0 + ty + (r << 3);
        float4 res = *(const float4*)&g_x[(size_t)row*80 + col];
        float4 v = make_float4(acc[r][0].x + bsv.x + res.x,
                               acc[r][0].y + bsv.y + res.y,
                               acc[r][1].x + bsv.z + res.z,
                               acc[r][1].y + bsv.w + res.w);
        *(float4*)&g_x[(size_t)row*80 + col] = v;
    }
}

// ---------------- attention: one block per (b, head), 512 threads ----------------
// smem: Qs[128][66], Ks[128][66], Vs[128][66], Ss[128][132] = 168960 bytes
#define ATTN_SMEM ((3*128*66 + 128*132) * 4)
__global__ void __launch_bounds__(512) attn_kernel() {
    extern __shared__ float sm[];
    float* Qs = sm;                  // 128*66
    float* Ks = Qs + 128*66;
    float* Vs = Ks + 128*66;
    float* Ss = Vs + 128*66;         // 128*132
    int bh = blockIdx.x;
    int b = bh >> 3, hh = bh & 7;
    int t = threadIdx.x;
    int tx = t & 15, ty = t >> 4;    // 16 x 32

    const float* qbase = g_qkv + (size_t)(b*NNODE)*1536 + hh*DHD;
    // stage Q, K, V row-major (stride 66) — float2, coalesced gmem reads
    for (int i = t; i < 128*32; i += 512) {
        int r = i >> 5, c2 = (i & 31) * 2;
        *(float2*)&Qs[r*66 + c2] = *(const float2*)(qbase +        (size_t)r*1536 + c2);
        *(float2*)&Ks[r*66 + c2] = *(const float2*)(qbase +  512 + (size_t)r*1536 + c2);
        *(float2*)&Vs[r*66 + c2] = *(const float2*)(qbase + 1024 + (size_t)r*1536 + c2);
    }
    const float* bb = g_bias + (size_t)b*NNODE*NNODE;
    for (int i = t; i < 128*128; i += 512) {
        Ss[(i >> 7)*132 + (i & 127)] = bb[i];
    }
    __syncthreads();

    // phase 1: S = bias + scale * Q K^T
    // thread: rows ty*4..+3, cols tx+16c (c=0..7); k packed in even/odd pairs
    {
        float2 acc[4][8];
        #pragma unroll
        for (int r = 0; r < 4; r++)
            #pragma unroll
            for (int c = 0; c < 8; c++) acc[r][c] = make_float2(0.f, 0.f);
        #pragma unroll 4
        for (int kk = 0; kk < 32; kk++) {
            float2 a2[4], k2[8];
            #pragma unroll
            for (int r = 0; r < 4; r++)
                a2[r] = *(float2*)&Qs[(ty*4 + r)*66 + 2*kk];
            #pragma unroll
            for (int c = 0; c < 8; c++)
                k2[c] = *(float2*)&Ks[(tx + 16*c)*66 + 2*kk];
            #pragma unroll
            for (int r = 0; r < 4; r++)
                #pragma unroll
                for (int c = 0; c < 8; c++)
                    acc[r][c] = ffma2(a2[r], k2[c], acc[r][c]);
        }
        #pragma unroll
        for (int r = 0; r < 4; r++)
            #pragma unroll
            for (int c = 0; c < 8; c++)
                Ss[(ty*4 + r)*132 + tx + 16*c] += (acc[r][c].x + acc[r][c].y) * 0.125f;
    }
    __syncthreads();

    // softmax: 16 warps x 8 rows each, lane handles 4 cols
    {
        int w = t >> 5, lane = t & 31;
        #pragma unroll
        for (int rr = 0; rr < 8; rr++) {
            int row = w*8 + rr;
            float4 v = *(float4*)&Ss[row*132 + lane*4];
            float mx = fmaxf(fmaxf(v.x, v.y), fmaxf(v.z, v.w));
            #pragma unroll
            for (int o = 16; o; o >>= 1) mx = fmaxf(mx, __shfl_xor_sync(0xffffffffu, mx, o));
            v.x = __expf(v.x - mx); v.y = __expf(v.y - mx);
            v.z = __expf(v.z - mx); v.w = __expf(v.w - mx);
            float s = v.x + v.y + v.z + v.w;
            #pragma unroll
            for (int o = 16; o; o >>= 1) s += __shfl_xor_sync(0xffffffffu, s, o);
            float inv = 1.f / s;
            v.x *= inv; v.y *= inv; v.z *= inv; v.w *= inv;
            *(float4*)&Ss[row*132 + lane*4] = v;
        }
    }
    __syncthreads();

    // phase 2: O = A V ; rows ty*4..+3, d = {2tx,2tx+1} and {2tx+32,2tx+33}
    {
        float2 oacc[4][2];
        #pragma unroll
        for (int r = 0; r < 4; r++) { oacc[r][0] = make_float2(0.f,0.f); oacc[r][1] = make_float2(0.f,0.f); }
        #pragma unroll 4
        for (int j = 0; j < 128; j++) {
            float2 v0 = *(float2*)&Vs[j*66 + 2*tx];
            float2 v1 = *(float2*)&Vs[j*66 + 32 + 2*tx];
            #pragma unroll
            for (int r = 0; r < 4; r++) {
                float a = Ss[(ty*4 + r)*132 + j];
                float2 aa = make_float2(a, a);
                oacc[r][0] = ffma2(aa, v0, oacc[r][0]);
                oacc[r][1] = ffma2(aa, v1, oacc[r][1]);
            }
        }
        float* obase = g_o + (size_t)(b*NNODE)*INNER + hh*DHD;
        #pragma unroll
        for (int r = 0; r < 4; r++) {
            int row = ty*4 + r;
            *(float2*)&obase[(size_t)row*INNER + 2*tx]      = oacc[r][0];
            *(float2*)&obase[(size_t)row*INNER + 32 + 2*tx] = oacc[r][1];
        }
    }
}

// ---------------- final: pool, LN, linear ----------------
__global__ void final_kernel(const float* __restrict__ gam, const float* __restrict__ bet,
                             const float* __restrict__ Wf, const float* __restrict__ bf,
                             float* __restrict__ out) {
    __shared__ float p[DLAT];
    int b = blockIdx.x, d = threadIdx.x;
    if (d < DLAT) {
        float s = 0.f;
        for (int n = 0; n < NNODE; n++) s += g_x[(size_t)((b << 7) + n)*DLAT + d];
        p[d] = s * (1.f/128.f);
    }
    __syncthreads();
    if (d == 0) {
        float m = 0.f;
        for (int i = 0; i < DLAT; i++) m += p[i];
        m *= (1.f/80.f);
        float v = 0.f;
        for (int i = 0; i < DLAT; i++) { float dd = p[i] - m; v += dd*dd; }
        v *= (1.f/80.f);
        float inv = rsqrtf(v + 1e-5f);
        float acc = bf[0];
        for (int i = 0; i < DLAT; i++)
            acc += ((p[i] - m)*inv*gam[i] + bet[i]) * Wf[i];
        out[b] = acc;
    }
}

// ---------------- launcher ----------------
extern "C" void kernel_launch(void* const* d_in, const int* in_sizes, int n_in,
                              void* d_out, int out_size) {
    const int*   spatial_pos = (const int*)d_in[0];
    const int*   edge_input  = (const int*)d_in[1];
    const int*   x_nodes     = (const int*)d_in[2];
    const int*   indeg       = (const int*)d_in[3];
    const int*   outdeg      = (const int*)d_in[4];
    const float* atom_emb    = (const float*)d_in[5];
    const float* indeg_emb   = (const float*)d_in[6];
    const float* outdeg_emb  = (const float*)d_in[7];
    const float* edge_emb    = (const float*)d_in[8];
    const float* edge_dis_w  = (const float*)d_in[9];
    const float* spatial_emb = (const float*)d_in[10];
    const float* ln1_g = (const float*)d_in[11];
    const float* ln1_b = (const float*)d_in[12];
    const float* Wq    = (const float*)d_in[13];
    const float* Wkv   = (const float*)d_in[14];
    const float* Wo    = (const float*)d_in[15];
    const float* bo    = (const float*)d_in[16];
    const float* ln2_g = (const float*)d_in[17];
    const float* ln2_b = (const float*)d_in[18];
    const float* W1    = (const float*)d_in[19];
    const float* b1    = (const float*)d_in[20];
    const float* W2    = (const float*)d_in[21];
    const float* b2    = (const float*)d_in[22];
    const float* lnf_g = (const float*)d_in[23];
    const float* lnf_b = (const float*)d_in[24];
    const float* Wf    = (const float*)d_in[25];
    const float* bf    = (const float*)d_in[26];
    float* out = (float*)d_out;

    cudaFuncSetAttribute(attn_kernel, cudaFuncAttributeMaxDynamicSharedMemorySize, ATTN_SMEM);
    cudaFuncSetAttribute(gemm_qkv_kernel, cudaFuncAttributeMaxDynamicSharedMemorySize, QKV_SMEM);

    bias_kernel<<<(BB*NNODE*NNODE)/256, 256>>>(spatial_pos, edge_input, edge_emb,
                                               edge_dis_w, spatial_emb);
    embed_kernel<<<ROWS, 80>>>(x_nodes, indeg, outdeg, atom_emb, indeg_emb, outdeg_emb);

    for (int l = 0; l < DEPTH; l++) {
        gemm_qkv_kernel<<<dim3(ROWS/64, 12), 128, QKV_SMEM>>>(
            Wq + (size_t)l*DLAT*INNER, Wkv + (size_t)l*DLAT*2*INNER,
            ln1_g + l*DLAT, ln1_b + l*DLAT);
        attn_kernel<<<BB*HEADS, 512, ATTN_SMEM>>>();
        gemm_resid_kernel<<<ROWS/64, 160>>>(Wo + (size_t)l*INNER*DLAT, bo + l*DLAT, 0);
        gemm_ffn1_kernel<<<dim3(ROWS/64, 3), 128>>>(W1 + (size_t)l*DLAT*FFD, b1 + l*FFD,
                                                    ln2_g + l*DLAT, ln2_b + l*DLAT);
        gemm_resid_kernel<<<ROWS/64, 160>>>(W2 + (size_t)l*FFD*DLAT, b2 + l*DLAT, 1);
    }
    final_kernel<<<BB, 80>>>(lnf_g, lnf_b, Wf, bf, out);
}